// round 15
// baseline (speedup 1.0000x reference)
#include <cuda_runtime.h>

#define NGRID   41088
#define PMAX    404
#define MDIM    192
#define KR      192
#define KF      96
#define BCN     1024
#define QPAD    128
#define TWO_PI_F 6.28318530717958647692f

typedef unsigned long long u64;
typedef unsigned int u32;

// Pre-folded stage-A output: (re,im) pairs, layout [m][kf][bc], kf in [0,96)
__device__ u64 g_rip[(size_t)MDIM * KF * BCN];   // A+ (DFT of ring-sum)
__device__ u64 g_rim[(size_t)MDIM * KF * BCN];   // A- (DFT of ring-diff)
// Stage-B staging: (re,im) pairs, layout [m][l][bc]
__device__ u64 g_st[(size_t)MDIM * MDIM * BCN];
// Double-folded x streams: [k1][q][par*2+pm][bc], u64 = (XA,XB) / (XC,XD)
__device__ u64 g_xf[(size_t)KF * QPAD * 4 * BCN];
// Folded basis: [k1][q][par][mc], u64 = (cos, sin)
__device__ u64 g_bf[(size_t)KF * QPAD * 2 * 96];

__device__ __forceinline__ u64 ffma2(u64 a, u64 b, u64 c) {
    u64 d; asm("fma.rn.f32x2 %0,%1,%2,%3;" : "=l"(d) : "l"(a), "l"(b), "l"(c)); return d;
}
__device__ __forceinline__ u64 fmul2(u64 a, u64 b) {
    u64 d; asm("mul.rn.f32x2 %0,%1,%2;" : "=l"(d) : "l"(a), "l"(b)); return d;
}
__device__ __forceinline__ u64 pk2(float lo, float hi) {
    u64 r; asm("mov.b64 %0,{%1,%2};" : "=l"(r) : "f"(lo), "f"(hi)); return r;
}
__device__ __forceinline__ void lds2(u64& a, u64& b, u32 addr) {
    asm volatile("ld.shared.v2.u64 {%0,%1},[%2];" : "=l"(a), "=l"(b) : "r"(addr));
}
__device__ __forceinline__ float4 lds4f(u32 addr) {
    float4 v;
    asm volatile("ld.shared.v4.f32 {%0,%1,%2,%3},[%4];"
                 : "=f"(v.x), "=f"(v.y), "=f"(v.z), "=f"(v.w) : "r"(addr));
    return v;
}
__device__ __forceinline__ void sts1(u32 addr, float a) {
    asm volatile("st.shared.f32 [%0],%1;" :: "r"(addr), "f"(a));
}
__device__ __forceinline__ u32 s2u(const void* p) {
    u32 a; asm("{.reg .u64 t; cvta.to.shared.u64 t,%1; cvt.u32.u64 %0,t;}" : "=r"(a) : "l"(p)); return a;
}
__device__ __forceinline__ void cpa16(u32 dst, const void* src, int bytes) {
    asm volatile("cp.async.cg.shared.global [%0],[%1],16,%2;" :: "r"(dst), "l"(src), "r"(bytes));
}
__device__ __forceinline__ void cpcommit() { asm volatile("cp.async.commit_group;"); }
__device__ __forceinline__ void cpwait0()  { asm volatile("cp.async.wait_group 0;"); }
__device__ __forceinline__ void cpwait1()  { asm volatile("cp.async.wait_group 1;"); }

// ---------------------------------------------------------------------------
// Fold-x: hemisphere ring fold (pre-DFT, by linearity) + double DFT fold.
// For ring pair (k1, 191-k1), q in [0, h2], h2 = nlon/4:
//   per ring: xpa=x[q]+x[nlon-q], xma=x[q]-x[nlon-q],
//             xpb=x[half-q]+x[half+q], xmb=x[half-q]-x[half+q]
//   XA=xpa+xpb (even-m re), XB=xma-xmb (even-m im),
//   XC=xpa-xpb (odd-m  re), XD=xma+xmb (odd-m  im)
//   edges: q=0 -> XA=x[0]+x[half], XC=x[0]-x[half], XB=XD=0
//          q=h2 -> XA=XC=x[h2]+x[3h2], XB=XD=x[h2]-x[3h2]
// Output streams for y+ = ring0+ring1 and y- = ring0-ring1.
// grid = (16 bc-tiles of 64, 96 pairs), block 256 (64 bc x 4 q-lanes).
// ---------------------------------------------------------------------------
extern "C" __global__ void __launch_bounds__(256)
sht_foldx(const float* __restrict__ x)
{
    const int bc = blockIdx.x * 64 + (threadIdx.x & 63);
    const int qg = threadIdx.x >> 6;        // 0..3
    const int k1 = blockIdx.y;
    const int nlon = 24 + 4 * k1;
    const int half = nlon >> 1, h2 = half >> 1;
    const int slon1 = 2 * k1 * k1 + 22 * k1;
    const int q2r = k1 + 1;
    const int slon2 = NGRID - (2 * q2r * q2r + 22 * q2r);
    const float* r0 = x + (size_t)bc * NGRID + slon1;
    const float* r1 = x + (size_t)bc * NGRID + slon2;
    u64* dst = g_xf + (size_t)k1 * QPAD * 4 * BCN + bc;

    for (int q = qg; q <= h2; q += 4) {
        float XA[2], XB[2], XC[2], XD[2];
#pragma unroll
        for (int r = 0; r < 2; r++) {
            const float* xr = r ? r1 : r0;
            float a = xr[q];
            if (q == 0) {
                float c = xr[half];
                XA[r] = a + c; XC[r] = a - c; XB[r] = 0.f; XD[r] = 0.f;
            } else if (q == h2) {
                float b = xr[nlon - q];
                XA[r] = a + b; XC[r] = a + b; XB[r] = a - b; XD[r] = a - b;
            } else {
                float b = xr[nlon - q];
                float c = xr[half - q], d = xr[half + q];
                float xpa = a + b, xma = a - b;
                float xpb = c + d, xmb = c - d;
                XA[r] = xpa + xpb; XB[r] = xma - xmb;
                XC[r] = xpa - xpb; XD[r] = xma + xmb;
            }
        }
        u64* dq = dst + (size_t)q * 4 * BCN;
        dq[0]           = pk2(XA[0] + XA[1], XB[0] + XB[1]);   // par0, y+
        dq[BCN]         = pk2(XA[0] - XA[1], XB[0] - XB[1]);   // par0, y-
        dq[2 * BCN]     = pk2(XC[0] + XC[1], XD[0] + XD[1]);   // par1, y+
        dq[3 * BCN]     = pk2(XC[0] - XC[1], XD[0] - XD[1]);   // par1, y-
    }
}

// ---------------------------------------------------------------------------
// Fold-basis: interleave (cos,sin) pairs, parity-compacted over m.
// g_bf[k1][q][par][mc] = (cos[k1,q,2mc+par], sin[k1,q,2mc+par])
// grid = 96 pairs, block 256.
// ---------------------------------------------------------------------------
extern "C" __global__ void __launch_bounds__(256)
sht_foldb(const float* __restrict__ cosb, const float* __restrict__ sinb)
{
    const int k1 = blockIdx.x;
    const int h2 = (24 + 4 * k1) >> 2;
    const int t  = threadIdx.x;
    const int qr = t >> 4;
    const int mq = (t & 15) * 4;
    const float* cb = cosb + (size_t)k1 * PMAX * MDIM;
    const float* sn = sinb + (size_t)k1 * PMAX * MDIM;

    for (int q0 = 0; q0 <= h2; q0 += 16) {
        int q = q0 + qr;
        if (q > h2) continue;
#pragma unroll
        for (int ms = 0; ms < 3; ms++) {
            int m = ms * 64 + mq;
            float4 c4 = *(const float4*)(cb + (size_t)q * MDIM + m);
            float4 s4 = *(const float4*)(sn + (size_t)q * MDIM + m);
            u64* d = g_bf + (size_t)(k1 * QPAD + q) * 2 * 96;
            int mc = m >> 1;
            d[mc]          = pk2(c4.x, s4.x);   // par 0
            d[mc + 1]      = pk2(c4.z, s4.z);
            d[96 + mc]     = pk2(c4.y, s4.y);   // par 1
            d[96 + mc + 1] = pk2(c4.w, s4.w);
        }
    }
}

// ---------------------------------------------------------------------------
// Stage A: double-folded DFT GEMM, operands pre-folded in gmem.
// grid = (16 bc-tiles of 64, 96 pairs big-first, 3 m-tiles of 64), 256 thr.
// Staging = pure cp.async (zero-fill beyond h2). Compute identical to r14.
// smem (80KB): CS[2][16q][2par][32mc u64] | XS[2][16q][2par][2pm][64bc u64]
// ---------------------------------------------------------------------------
extern "C" __global__ void __launch_bounds__(256, 2)
sht_stageA()
{
    extern __shared__ __align__(16) unsigned char smA[];   // 81920 B
    const int t   = threadIdx.x;
    const int bc0 = blockIdx.x * 64;
    const int k1  = 95 - blockIdx.y;        // big rings first
    const int m0  = blockIdx.z * 64;

    int mmax = 12 + 2 * k1;
    if (mmax > MDIM - 1) mmax = MDIM - 1;
    if (m0 > mmax) return;
    const int h2 = (24 + 4 * k1) >> 2;
    const int ntiles = (h2 + 16) >> 4;
    const int mc0 = m0 >> 1;

    const u32 sb = s2u(smA);
    const u32 XS = sb + 16384;

    // compute roles
    const int w = t >> 5, lane = t & 31;
    const int par = w & 1, mch = (w >> 1) & 1, bw = w >> 2;
    const int lm = lane >> 3, lb = lane & 7;

    u64 acc0[4][4], acc1[4][4];
#pragma unroll
    for (int j = 0; j < 4; j++)
#pragma unroll
        for (int i = 0; i < 4; i++) { acc0[j][i] = 0ull; acc1[j][i] = 0ull; }

    auto cpa_tile = [&](int buf, int q0) {
#pragma unroll
        for (int i = 0; i < 2; i++) {       // CS: 512 chunks of 16B
            int c = t * 2 + i;
            int q = c >> 5, rest = c & 31;
            int pr = rest >> 4, ci = rest & 15;
            int qq = q0 + q;
            int bytes = (qq <= h2) ? 16 : 0;
            const u64* src = g_bf + ((size_t)(k1 * QPAD + qq) * 2 + pr) * 96 + mc0 + ci * 2;
            cpa16(sb + buf * 8192 + q * 512 + pr * 256 + ci * 16, src, bytes);
        }
#pragma unroll
        for (int i = 0; i < 8; i++) {       // XS: 2048 chunks of 16B
            int c = t * 8 + i;
            int q = c >> 7, rest = c & 127;
            int pp = rest >> 5, ci = rest & 31;   // pp = par*2+pm
            int qq = q0 + q;
            int bytes = (qq <= h2) ? 16 : 0;
            const u64* src = g_xf + ((size_t)(k1 * QPAD + qq) * 4 + pp) * BCN + bc0 + ci * 2;
            cpa16(XS + buf * 32768 + q * 2048 + pp * 512 + ci * 16, src, bytes);
        }
        cpcommit();
    };

    auto compute = [&](int buf) {
        u32 cs = sb + buf * 8192 + par * 256 + (mch * 16 + lm * 4) * 8;
        u32 xs = XS + buf * 32768 + par * 1024 + bw * 256 + lb * 16;
#pragma unroll
        for (int qq = 0; qq < 16; ++qq) {
            u64 b0, b1, b2, b3;
            lds2(b0, b1, cs + qq * 512);
            lds2(b2, b3, cs + qq * 512 + 16);
            u64 v0, v1, v2, v3, u0, u1, u2, u3;
            lds2(v0, v1, xs + qq * 2048);          // y+ bc {2lb,2lb+1}
            lds2(v2, v3, xs + qq * 2048 + 128);    // y+ bc +16
            lds2(u0, u1, xs + qq * 2048 + 512);    // y-
            lds2(u2, u3, xs + qq * 2048 + 640);
            acc0[0][0] = ffma2(b0, v0, acc0[0][0]);
            acc0[0][1] = ffma2(b0, v1, acc0[0][1]);
            acc0[0][2] = ffma2(b0, v2, acc0[0][2]);
            acc0[0][3] = ffma2(b0, v3, acc0[0][3]);
            acc0[1][0] = ffma2(b1, v0, acc0[1][0]);
            acc0[1][1] = ffma2(b1, v1, acc0[1][1]);
            acc0[1][2] = ffma2(b1, v2, acc0[1][2]);
            acc0[1][3] = ffma2(b1, v3, acc0[1][3]);
            acc0[2][0] = ffma2(b2, v0, acc0[2][0]);
            acc0[2][1] = ffma2(b2, v1, acc0[2][1]);
            acc0[2][2] = ffma2(b2, v2, acc0[2][2]);
            acc0[2][3] = ffma2(b2, v3, acc0[2][3]);
            acc0[3][0] = ffma2(b3, v0, acc0[3][0]);
            acc0[3][1] = ffma2(b3, v1, acc0[3][1]);
            acc0[3][2] = ffma2(b3, v2, acc0[3][2]);
            acc0[3][3] = ffma2(b3, v3, acc0[3][3]);
            acc1[0][0] = ffma2(b0, u0, acc1[0][0]);
            acc1[0][1] = ffma2(b0, u1, acc1[0][1]);
            acc1[0][2] = ffma2(b0, u2, acc1[0][2]);
            acc1[0][3] = ffma2(b0, u3, acc1[0][3]);
            acc1[1][0] = ffma2(b1, u0, acc1[1][0]);
            acc1[1][1] = ffma2(b1, u1, acc1[1][1]);
            acc1[1][2] = ffma2(b1, u2, acc1[1][2]);
            acc1[1][3] = ffma2(b1, u3, acc1[1][3]);
            acc1[2][0] = ffma2(b2, u0, acc1[2][0]);
            acc1[2][1] = ffma2(b2, u1, acc1[2][1]);
            acc1[2][2] = ffma2(b2, u2, acc1[2][2]);
            acc1[2][3] = ffma2(b2, u3, acc1[2][3]);
            acc1[3][0] = ffma2(b3, u0, acc1[3][0]);
            acc1[3][1] = ffma2(b3, u1, acc1[3][1]);
            acc1[3][2] = ffma2(b3, u2, acc1[3][2]);
            acc1[3][3] = ffma2(b3, u3, acc1[3][3]);
        }
    };

    cpa_tile(0, 0);
    for (int ti = 0; ti < ntiles; ++ti) {
        bool nx = (ti + 1) < ntiles;
        if (nx) { cpa_tile((ti + 1) & 1, (ti + 1) << 4); cpwait1(); }
        else    { cpwait0(); }
        __syncthreads();
        compute(ti & 1);
        __syncthreads();
    }

    // epilogue: scale 2*pi, STG.128 (acc0 -> A+, acc1 -> A-)
    const u64 tp2 = pk2(TWO_PI_F, TWO_PI_F);
#pragma unroll
    for (int j = 0; j < 4; j++) {
        int m = m0 + 2 * (mch * 16 + lm * 4 + j) + par;
        size_t base = ((size_t)m * KF + k1) * BCN + bc0 + bw * 32 + 2 * lb;
        u64* op = g_rip + base;
        u64* om = g_rim + base;
        ulonglong2 wp0, wp1, wm0, wm1;
        wp0.x = fmul2(acc0[j][0], tp2);
        wp0.y = fmul2(acc0[j][1], tp2);
        wp1.x = fmul2(acc0[j][2], tp2);
        wp1.y = fmul2(acc0[j][3], tp2);
        wm0.x = fmul2(acc1[j][0], tp2);
        wm0.y = fmul2(acc1[j][1], tp2);
        wm1.x = fmul2(acc1[j][2], tp2);
        wm1.y = fmul2(acc1[j][3], tp2);
        *(ulonglong2*)op        = wp0;
        *(ulonglong2*)(op + 16) = wp1;
        *(ulonglong2*)om        = wm0;
        *(ulonglong2*)(om + 16) = wm1;
    }
}

// ---------------------------------------------------------------------------
// Stage B: per-m GEMM on pre-folded operands, parity-coherent warps.
//   st[m,l,bc] = sum_{k in [klo,95]} W[m,l,k] * ( (l+m) even ? A+[k] : A-[k] )
// grid = (16 bc-tiles of 64, 3 l-tiles of 64, 192 m), block = 128.
// ---------------------------------------------------------------------------
extern "C" __global__ void __launch_bounds__(128, 4)
sht_stageB(const float* __restrict__ weight)
{
    __shared__ __align__(16) unsigned char sm[4 * 16 * 512 + 2 * 16 * 256];  // 40960
    const int t   = threadIdx.x;
    const int bc0 = blockIdx.x * 64;
    const int l0  = blockIdx.y * 64;
    const int m   = blockIdx.z;
    if (l0 + 63 < m) return;                // zero triangle: handled by transpose

    const int klo = (m <= 12) ? 0 : ((m - 11) >> 1);
    const int kb0 = klo & ~15;
    const int nkt = ((95 - kb0) >> 4) + 1;

    const u32 sb  = s2u(sm);
    const u32 APS = sb;
    const u32 AMS = sb + 16384;
    const u32 WS  = sb + 32768;

    const int lr = t >> 1, kq = (t & 1) * 8;
    const int wpar = (lr + m) & 1, wlc = lr >> 1;

    const int w = t >> 5, lane = t & 31;
    const int pw  = w & 1;
    const int h   = w >> 1;
    const int lc0 = (lane >> 3) * 8;
    const int bto = h * 32 + (lane & 7) * 4;
    const int dlt = pw ^ (m & 1);

    const float* wrow   = weight + ((size_t)m * MDIM + l0 + lr) * KR;
    const u64*   apbase = g_rip + ((size_t)m * KF) * BCN + bc0;
    const u64*   ambase = g_rim + ((size_t)m * KF) * BCN + bc0;

    u64 acc[8][4];
#pragma unroll
    for (int j = 0; j < 8; j++)
#pragma unroll
        for (int i = 0; i < 4; i++) acc[j][i] = 0ull;

    float4 w40, w41;
    auto cpa_tile = [&](int buf, int kb) {
#pragma unroll
        for (int c = 0; c < 4; c++) {
            int chunk = t * 4 + c;
            int kk = chunk >> 5, col = chunk & 31;
            int kg = kb + kk;
            int bytes = (kg >= klo) ? 16 : 0;
            cpa16(APS + buf * 8192 + kk * 512 + col * 16,
                  apbase + (size_t)kg * BCN + col * 2, bytes);
            cpa16(AMS + buf * 8192 + kk * 512 + col * 16,
                  ambase + (size_t)kg * BCN + col * 2, bytes);
        }
        cpcommit();
    };
    auto ldW = [&](int kb) {
        w40 = *(const float4*)(wrow + kb + kq);
        w41 = *(const float4*)(wrow + kb + kq + 4);
    };
    auto stW = [&](int buf) {
        u32 ws = WS + buf * 4096 + wpar * 128 + wlc * 4;
        sts1(ws + (kq + 0) * 256, w40.x);
        sts1(ws + (kq + 1) * 256, w40.y);
        sts1(ws + (kq + 2) * 256, w40.z);
        sts1(ws + (kq + 3) * 256, w40.w);
        sts1(ws + (kq + 4) * 256, w41.x);
        sts1(ws + (kq + 5) * 256, w41.y);
        sts1(ws + (kq + 6) * 256, w41.z);
        sts1(ws + (kq + 7) * 256, w41.w);
    };

    const u32 AT = pw ? AMS : APS;

    auto compute = [&](int buf) {
        u32 as_ = AT + buf * 8192 + bto * 8;
        u32 ws  = WS + buf * 4096 + pw * 128 + lc0 * 4;
#pragma unroll
        for (int kk = 0; kk < 16; ++kk) {
            u64 a[4];
            lds2(a[0], a[1], as_ + kk * 512);
            lds2(a[2], a[3], as_ + kk * 512 + 16);
            float4 f0 = lds4f(ws + kk * 256);
            float4 f1 = lds4f(ws + kk * 256 + 16);
            const float fw[8] = {f0.x, f0.y, f0.z, f0.w, f1.x, f1.y, f1.z, f1.w};
#pragma unroll
            for (int j = 0; j < 8; j++) {
                u64 ww = pk2(fw[j], fw[j]);
#pragma unroll
                for (int i = 0; i < 4; i++)
                    acc[j][i] = ffma2(a[i], ww, acc[j][i]);
            }
        }
    };

    cpa_tile(0, kb0);
    ldW(kb0);
    stW(0);
    cpwait0();
    __syncthreads();
    for (int ti = 0; ti < nkt; ++ti) {
        int kb = kb0 + ((ti + 1) << 4);
        bool nx = (ti + 1) < nkt;
        if (nx) { cpa_tile((ti + 1) & 1, kb); ldW(kb); }
        compute(ti & 1);
        if (nx) { stW((ti + 1) & 1); cpwait0(); }
        __syncthreads();
    }

#pragma unroll
    for (int j = 0; j < 8; j++) {
        int l = l0 + 2 * (lc0 + j) + dlt;
        u64* o = g_st + (((size_t)m * MDIM) + l) * BCN + bc0 + bto;
        ulonglong2 w0, w1;
        w0.x = acc[j][0]; w0.y = acc[j][1];
        w1.x = acc[j][2]; w1.y = acc[j][3];
        *(ulonglong2*)o       = w0;
        *(ulonglong2*)(o + 2) = w1;
    }
}

// ---------------------------------------------------------------------------
// Transpose: out[bc][l][m] <- g_st[m][l][bc]; zero for l < m.
// ---------------------------------------------------------------------------
extern "C" __global__ void __launch_bounds__(256)
sht_transpose(u64* __restrict__ out)
{
    __shared__ u64 smt[32][65];
    const int t   = threadIdx.x;
    const int bc0 = blockIdx.x * 64;
    const int m0  = blockIdx.y * 32;
    const int l   = blockIdx.z;

    const int mr  = t >> 5;
    const int bcc = (t & 31) * 2;
#pragma unroll
    for (int r = 0; r < 4; ++r) {
        int ml = mr + r * 8;
        ulonglong2 v;
        if (l >= m0 + ml)
            v = *(const ulonglong2*)(g_st + (((size_t)(m0 + ml)) * MDIM + l) * BCN + bc0 + bcc);
        else
            v = make_ulonglong2(0ull, 0ull);
        smt[ml][bcc]     = v.x;
        smt[ml][bcc + 1] = v.y;
    }
    __syncthreads();

    const int bcr = t >> 4;
    const int mc  = (t & 15) * 2;
#pragma unroll
    for (int r = 0; r < 4; ++r) {
        int bcl = bcr + r * 16;
        ulonglong2 v;
        v.x = smt[mc][bcl];
        v.y = smt[mc + 1][bcl];
        *(ulonglong2*)(out + (((size_t)(bc0 + bcl)) * MDIM + l) * MDIM + m0 + mc) = v;
    }
}

// ---------------------------------------------------------------------------

extern "C" void kernel_launch(void* const* d_in, const int* in_sizes, int n_in,
                              void* d_out, int out_size)
{
    (void)in_sizes; (void)n_in; (void)out_size;
    const float* x      = (const float*)d_in[0];
    const float* weight = (const float*)d_in[1];
    const float* cosb   = (const float*)d_in[2];
    const float* sinb   = (const float*)d_in[3];

    dim3 gFX(16, 96);
    sht_foldx<<<gFX, 256>>>(x);

    sht_foldb<<<96, 256>>>(cosb, sinb);

    const int smemA = 81920;
    cudaFuncSetAttribute(sht_stageA, cudaFuncAttributeMaxDynamicSharedMemorySize, smemA);
    dim3 gA(16, 96, 3);
    sht_stageA<<<gA, 256, smemA>>>();

    dim3 gB(16, 3, 192);
    sht_stageB<<<gB, 128>>>(weight);

    dim3 gT(16, 6, 192);
    sht_transpose<<<gT, 256>>>((u64*)d_out);
}

// round 16
// speedup vs baseline: 1.1472x; 1.1472x over previous
#include <cuda_runtime.h>

#define NGRID   41088
#define PMAX    404
#define MDIM    192
#define KR      192
#define KF      96
#define BCN     1024
#define QPAD    128
#define XROWP   408
#define TWO_PI_F 6.28318530717958647692f

typedef unsigned long long u64;
typedef unsigned int u32;

// Pre-folded stage-A output: (re,im) pairs, layout [m][kf][bc], kf in [0,96)
__device__ u64 g_rip[(size_t)MDIM * KF * BCN];   // A+ (DFT of ring-sum)
__device__ u64 g_rim[(size_t)MDIM * KF * BCN];   // A- (DFT of ring-diff)
// Stage-B staging: (re,im) pairs, layout [m][l][bc]
__device__ u64 g_st[(size_t)MDIM * MDIM * BCN];
// Double-folded x streams: [k1][q][par*2+pm][bc], u64 = (XA,XB) / (XC,XD)
__device__ u64 g_xf[(size_t)KF * QPAD * 4 * BCN];
// Folded basis: [k1][q][par][mc], u64 = (cos, sin)
__device__ u64 g_bf[(size_t)KF * QPAD * 2 * 96];

__device__ __forceinline__ u64 ffma2(u64 a, u64 b, u64 c) {
    u64 d; asm("fma.rn.f32x2 %0,%1,%2,%3;" : "=l"(d) : "l"(a), "l"(b), "l"(c)); return d;
}
__device__ __forceinline__ u64 fmul2(u64 a, u64 b) {
    u64 d; asm("mul.rn.f32x2 %0,%1,%2;" : "=l"(d) : "l"(a), "l"(b)); return d;
}
__device__ __forceinline__ u64 pk2(float lo, float hi) {
    u64 r; asm("mov.b64 %0,{%1,%2};" : "=l"(r) : "f"(lo), "f"(hi)); return r;
}
__device__ __forceinline__ void lds2(u64& a, u64& b, u32 addr) {
    asm volatile("ld.shared.v2.u64 {%0,%1},[%2];" : "=l"(a), "=l"(b) : "r"(addr));
}
__device__ __forceinline__ float4 lds4f(u32 addr) {
    float4 v;
    asm volatile("ld.shared.v4.f32 {%0,%1,%2,%3},[%4];"
                 : "=f"(v.x), "=f"(v.y), "=f"(v.z), "=f"(v.w) : "r"(addr));
    return v;
}
__device__ __forceinline__ void sts1(u32 addr, float a) {
    asm volatile("st.shared.f32 [%0],%1;" :: "r"(addr), "f"(a));
}
__device__ __forceinline__ u32 s2u(const void* p) {
    u32 a; asm("{.reg .u64 t; cvta.to.shared.u64 t,%1; cvt.u32.u64 %0,t;}" : "=r"(a) : "l"(p)); return a;
}
__device__ __forceinline__ void cpa16(u32 dst, const void* src, int bytes) {
    asm volatile("cp.async.cg.shared.global [%0],[%1],16,%2;" :: "r"(dst), "l"(src), "r"(bytes));
}
__device__ __forceinline__ void cpcommit() { asm volatile("cp.async.commit_group;"); }
__device__ __forceinline__ void cpwait0()  { asm volatile("cp.async.wait_group 0;"); }
__device__ __forceinline__ void cpwait1()  { asm volatile("cp.async.wait_group 1;"); }

// ---------------------------------------------------------------------------
// Fold-x (coalesced): hemisphere ring fold + double DFT fold.
// Block = (16-bc group, k1). Phase 1: smem-stage 32 rows (16bc x 2rings) with
// 128B-coalesced float4 loads. Phase 2: lanes bc-contiguous, 128B store bursts.
//   XA=xpa+xpb (even-m re), XB=xma-xmb (even-m im),
//   XC=xpa-xpb (odd-m  re), XD=xma+xmb (odd-m  im), q in [0, h2]
//   edges: q=0 -> XA=x0+x[half], XC=x0-x[half], XB=XD=0
//          q=h2 -> XA=XC=x[h2]+x[3h2], XB=XD=x[h2]-x[3h2]
// Streams: (par0,y+),(par0,y-),(par1,y+),(par1,y-) at [k1][q][s][bc].
// ---------------------------------------------------------------------------
extern "C" __global__ void __launch_bounds__(256)
sht_foldx(const float* __restrict__ x)
{
    __shared__ float xs[32][XROWP];
    const int k1  = blockIdx.y;
    const int bc0 = blockIdx.x * 16;
    const int nlon = 24 + 4 * k1;
    const int half = nlon >> 1, h2 = half >> 1;
    const int slon1 = 2 * k1 * k1 + 22 * k1;
    const int q2r = k1 + 1;
    const int slon2 = NGRID - (2 * q2r * q2r + 22 * q2r);

    // phase 1: coalesced row staging
    {
        const int row = threadIdx.x >> 3;        // 0..31
        const int l8  = threadIdx.x & 7;
        const int bc  = bc0 + (row & 15);
        const int ring = row >> 4;
        const float* src = x + (size_t)bc * NGRID + (ring ? slon2 : slon1);
        for (int p = l8 * 4; p < nlon; p += 32)
            *(float4*)&xs[row][p] = *(const float4*)&src[p];
    }
    __syncthreads();

    // phase 2: fold + write (bc-contiguous lanes)
    const int bcl = threadIdx.x & 15;
    const int qs  = threadIdx.x >> 4;            // 0..15
    const float* r0 = xs[bcl];
    const float* r1 = xs[16 + bcl];
    u64* dst = g_xf + (size_t)k1 * QPAD * 4 * BCN + bc0 + bcl;

    for (int q = qs; q <= h2; q += 16) {
        float XA[2], XB[2], XC[2], XD[2];
#pragma unroll
        for (int r = 0; r < 2; r++) {
            const float* xr = r ? r1 : r0;
            float a = xr[q];
            if (q == 0) {
                float c = xr[half];
                XA[r] = a + c; XC[r] = a - c; XB[r] = 0.f; XD[r] = 0.f;
            } else if (q == h2) {
                float b = xr[nlon - q];
                XA[r] = a + b; XC[r] = a + b; XB[r] = a - b; XD[r] = a - b;
            } else {
                float b = xr[nlon - q];
                float c = xr[half - q], d = xr[half + q];
                float xpa = a + b, xma = a - b;
                float xpb = c + d, xmb = c - d;
                XA[r] = xpa + xpb; XB[r] = xma - xmb;
                XC[r] = xpa - xpb; XD[r] = xma + xmb;
            }
        }
        u64* dq = dst + (size_t)q * 4 * BCN;
        dq[0]       = pk2(XA[0] + XA[1], XB[0] + XB[1]);   // par0, y+
        dq[BCN]     = pk2(XA[0] - XA[1], XB[0] - XB[1]);   // par0, y-
        dq[2 * BCN] = pk2(XC[0] + XC[1], XD[0] + XD[1]);   // par1, y+
        dq[3 * BCN] = pk2(XC[0] - XC[1], XD[0] - XD[1]);   // par1, y-
    }
}

// ---------------------------------------------------------------------------
// Fold-basis: interleave (cos,sin) pairs, parity-compacted over m.
// ---------------------------------------------------------------------------
extern "C" __global__ void __launch_bounds__(256)
sht_foldb(const float* __restrict__ cosb, const float* __restrict__ sinb)
{
    const int k1 = blockIdx.x;
    const int h2 = (24 + 4 * k1) >> 2;
    const int t  = threadIdx.x;
    const int qr = t >> 4;
    const int mq = (t & 15) * 4;
    const float* cb = cosb + (size_t)k1 * PMAX * MDIM;
    const float* sn = sinb + (size_t)k1 * PMAX * MDIM;

    for (int q0 = 0; q0 <= h2; q0 += 16) {
        int q = q0 + qr;
        if (q > h2) continue;
#pragma unroll
        for (int ms = 0; ms < 3; ms++) {
            int m = ms * 64 + mq;
            float4 c4 = *(const float4*)(cb + (size_t)q * MDIM + m);
            float4 s4 = *(const float4*)(sn + (size_t)q * MDIM + m);
            u64* d = g_bf + (size_t)(k1 * QPAD + q) * 2 * 96;
            int mc = m >> 1;
            d[mc]          = pk2(c4.x, s4.x);
            d[mc + 1]      = pk2(c4.z, s4.z);
            d[96 + mc]     = pk2(c4.y, s4.y);
            d[96 + mc + 1] = pk2(c4.w, s4.w);
        }
    }
}

// ---------------------------------------------------------------------------
// Stage A: double-folded DFT GEMM, operands pre-folded in gmem.
// grid = (3 m-tiles, 16 bc-tiles, 96 pairs big-first): the 3 m-tile blocks
// sharing one g_xf slice are bid-adjacent -> L2-resident, no DRAM duplication.
// smem (80KB): CS[2][16q][2par][32mc u64] | XS[2][16q][2par][2pm][64bc u64]
// ---------------------------------------------------------------------------
extern "C" __global__ void __launch_bounds__(256, 2)
sht_stageA()
{
    extern __shared__ __align__(16) unsigned char smA[];   // 81920 B
    const int t   = threadIdx.x;
    const int m0  = blockIdx.x * 64;
    const int bc0 = blockIdx.y * 64;
    const int k1  = 95 - blockIdx.z;        // big rings first

    int mmax = 12 + 2 * k1;
    if (mmax > MDIM - 1) mmax = MDIM - 1;
    if (m0 > mmax) return;
    const int h2 = (24 + 4 * k1) >> 2;
    const int ntiles = (h2 + 16) >> 4;
    const int mc0 = m0 >> 1;

    const u32 sb = s2u(smA);
    const u32 XS = sb + 16384;

    const int w = t >> 5, lane = t & 31;
    const int par = w & 1, mch = (w >> 1) & 1, bw = w >> 2;
    const int lm = lane >> 3, lb = lane & 7;

    u64 acc0[4][4], acc1[4][4];
#pragma unroll
    for (int j = 0; j < 4; j++)
#pragma unroll
        for (int i = 0; i < 4; i++) { acc0[j][i] = 0ull; acc1[j][i] = 0ull; }

    auto cpa_tile = [&](int buf, int q0) {
#pragma unroll
        for (int i = 0; i < 2; i++) {       // CS: 512 chunks of 16B
            int c = t * 2 + i;
            int q = c >> 5, rest = c & 31;
            int pr = rest >> 4, ci = rest & 15;
            int qq = q0 + q;
            int bytes = (qq <= h2) ? 16 : 0;
            const u64* src = g_bf + ((size_t)(k1 * QPAD + qq) * 2 + pr) * 96 + mc0 + ci * 2;
            cpa16(sb + buf * 8192 + q * 512 + pr * 256 + ci * 16, src, bytes);
        }
#pragma unroll
        for (int i = 0; i < 8; i++) {       // XS: 2048 chunks of 16B
            int c = t * 8 + i;
            int q = c >> 7, rest = c & 127;
            int pp = rest >> 5, ci = rest & 31;
            int qq = q0 + q;
            int bytes = (qq <= h2) ? 16 : 0;
            const u64* src = g_xf + ((size_t)(k1 * QPAD + qq) * 4 + pp) * BCN + bc0 + ci * 2;
            cpa16(XS + buf * 32768 + q * 2048 + pp * 512 + ci * 16, src, bytes);
        }
        cpcommit();
    };

    auto compute = [&](int buf) {
        u32 cs = sb + buf * 8192 + par * 256 + (mch * 16 + lm * 4) * 8;
        u32 xs = XS + buf * 32768 + par * 1024 + bw * 256 + lb * 16;
#pragma unroll
        for (int qq = 0; qq < 16; ++qq) {
            u64 b0, b1, b2, b3;
            lds2(b0, b1, cs + qq * 512);
            lds2(b2, b3, cs + qq * 512 + 16);
            u64 v0, v1, v2, v3, u0, u1, u2, u3;
            lds2(v0, v1, xs + qq * 2048);
            lds2(v2, v3, xs + qq * 2048 + 128);
            lds2(u0, u1, xs + qq * 2048 + 512);
            lds2(u2, u3, xs + qq * 2048 + 640);
            acc0[0][0] = ffma2(b0, v0, acc0[0][0]);
            acc0[0][1] = ffma2(b0, v1, acc0[0][1]);
            acc0[0][2] = ffma2(b0, v2, acc0[0][2]);
            acc0[0][3] = ffma2(b0, v3, acc0[0][3]);
            acc0[1][0] = ffma2(b1, v0, acc0[1][0]);
            acc0[1][1] = ffma2(b1, v1, acc0[1][1]);
            acc0[1][2] = ffma2(b1, v2, acc0[1][2]);
            acc0[1][3] = ffma2(b1, v3, acc0[1][3]);
            acc0[2][0] = ffma2(b2, v0, acc0[2][0]);
            acc0[2][1] = ffma2(b2, v1, acc0[2][1]);
            acc0[2][2] = ffma2(b2, v2, acc0[2][2]);
            acc0[2][3] = ffma2(b2, v3, acc0[2][3]);
            acc0[3][0] = ffma2(b3, v0, acc0[3][0]);
            acc0[3][1] = ffma2(b3, v1, acc0[3][1]);
            acc0[3][2] = ffma2(b3, v2, acc0[3][2]);
            acc0[3][3] = ffma2(b3, v3, acc0[3][3]);
            acc1[0][0] = ffma2(b0, u0, acc1[0][0]);
            acc1[0][1] = ffma2(b0, u1, acc1[0][1]);
            acc1[0][2] = ffma2(b0, u2, acc1[0][2]);
            acc1[0][3] = ffma2(b0, u3, acc1[0][3]);
            acc1[1][0] = ffma2(b1, u0, acc1[1][0]);
            acc1[1][1] = ffma2(b1, u1, acc1[1][1]);
            acc1[1][2] = ffma2(b1, u2, acc1[1][2]);
            acc1[1][3] = ffma2(b1, u3, acc1[1][3]);
            acc1[2][0] = ffma2(b2, u0, acc1[2][0]);
            acc1[2][1] = ffma2(b2, u1, acc1[2][1]);
            acc1[2][2] = ffma2(b2, u2, acc1[2][2]);
            acc1[2][3] = ffma2(b2, u3, acc1[2][3]);
            acc1[3][0] = ffma2(b3, u0, acc1[3][0]);
            acc1[3][1] = ffma2(b3, u1, acc1[3][1]);
            acc1[3][2] = ffma2(b3, u2, acc1[3][2]);
            acc1[3][3] = ffma2(b3, u3, acc1[3][3]);
        }
    };

    cpa_tile(0, 0);
    for (int ti = 0; ti < ntiles; ++ti) {
        bool nx = (ti + 1) < ntiles;
        if (nx) { cpa_tile((ti + 1) & 1, (ti + 1) << 4); cpwait1(); }
        else    { cpwait0(); }
        __syncthreads();
        compute(ti & 1);
        __syncthreads();
    }

    const u64 tp2 = pk2(TWO_PI_F, TWO_PI_F);
#pragma unroll
    for (int j = 0; j < 4; j++) {
        int m = m0 + 2 * (mch * 16 + lm * 4 + j) + par;
        size_t base = ((size_t)m * KF + k1) * BCN + bc0 + bw * 32 + 2 * lb;
        u64* op = g_rip + base;
        u64* om = g_rim + base;
        ulonglong2 wp0, wp1, wm0, wm1;
        wp0.x = fmul2(acc0[j][0], tp2);
        wp0.y = fmul2(acc0[j][1], tp2);
        wp1.x = fmul2(acc0[j][2], tp2);
        wp1.y = fmul2(acc0[j][3], tp2);
        wm0.x = fmul2(acc1[j][0], tp2);
        wm0.y = fmul2(acc1[j][1], tp2);
        wm1.x = fmul2(acc1[j][2], tp2);
        wm1.y = fmul2(acc1[j][3], tp2);
        *(ulonglong2*)op        = wp0;
        *(ulonglong2*)(op + 16) = wp1;
        *(ulonglong2*)om        = wm0;
        *(ulonglong2*)(om + 16) = wm1;
    }
}

// ---------------------------------------------------------------------------
// Stage B: per-m GEMM on pre-folded operands, parity-coherent warps.
// grid = (3 l-tiles, 16 bc-tiles, 192 m): the blocks sharing one m-band are
// bid-adjacent -> band stays L2-resident.
// ---------------------------------------------------------------------------
extern "C" __global__ void __launch_bounds__(128, 4)
sht_stageB(const float* __restrict__ weight)
{
    __shared__ __align__(16) unsigned char sm[4 * 16 * 512 + 2 * 16 * 256];  // 40960
    const int t   = threadIdx.x;
    const int l0  = blockIdx.x * 64;
    const int bc0 = blockIdx.y * 64;
    const int m   = blockIdx.z;
    if (l0 + 63 < m) return;                // zero triangle: handled by transpose

    const int klo = (m <= 12) ? 0 : ((m - 11) >> 1);
    const int kb0 = klo & ~15;
    const int nkt = ((95 - kb0) >> 4) + 1;

    const u32 sb  = s2u(sm);
    const u32 APS = sb;
    const u32 AMS = sb + 16384;
    const u32 WS  = sb + 32768;

    const int lr = t >> 1, kq = (t & 1) * 8;
    const int wpar = (lr + m) & 1, wlc = lr >> 1;

    const int w = t >> 5, lane = t & 31;
    const int pw  = w & 1;
    const int h   = w >> 1;
    const int lc0 = (lane >> 3) * 8;
    const int bto = h * 32 + (lane & 7) * 4;
    const int dlt = pw ^ (m & 1);

    const float* wrow   = weight + ((size_t)m * MDIM + l0 + lr) * KR;
    const u64*   apbase = g_rip + ((size_t)m * KF) * BCN + bc0;
    const u64*   ambase = g_rim + ((size_t)m * KF) * BCN + bc0;

    u64 acc[8][4];
#pragma unroll
    for (int j = 0; j < 8; j++)
#pragma unroll
        for (int i = 0; i < 4; i++) acc[j][i] = 0ull;

    float4 w40, w41;
    auto cpa_tile = [&](int buf, int kb) {
#pragma unroll
        for (int c = 0; c < 4; c++) {
            int chunk = t * 4 + c;
            int kk = chunk >> 5, col = chunk & 31;
            int kg = kb + kk;
            int bytes = (kg >= klo) ? 16 : 0;
            cpa16(APS + buf * 8192 + kk * 512 + col * 16,
                  apbase + (size_t)kg * BCN + col * 2, bytes);
            cpa16(AMS + buf * 8192 + kk * 512 + col * 16,
                  ambase + (size_t)kg * BCN + col * 2, bytes);
        }
        cpcommit();
    };
    auto ldW = [&](int kb) {
        w40 = *(const float4*)(wrow + kb + kq);
        w41 = *(const float4*)(wrow + kb + kq + 4);
    };
    auto stW = [&](int buf) {
        u32 ws = WS + buf * 4096 + wpar * 128 + wlc * 4;
        sts1(ws + (kq + 0) * 256, w40.x);
        sts1(ws + (kq + 1) * 256, w40.y);
        sts1(ws + (kq + 2) * 256, w40.z);
        sts1(ws + (kq + 3) * 256, w40.w);
        sts1(ws + (kq + 4) * 256, w41.x);
        sts1(ws + (kq + 5) * 256, w41.y);
        sts1(ws + (kq + 6) * 256, w41.z);
        sts1(ws + (kq + 7) * 256, w41.w);
    };

    const u32 AT = pw ? AMS : APS;

    auto compute = [&](int buf) {
        u32 as_ = AT + buf * 8192 + bto * 8;
        u32 ws  = WS + buf * 4096 + pw * 128 + lc0 * 4;
#pragma unroll
        for (int kk = 0; kk < 16; ++kk) {
            u64 a[4];
            lds2(a[0], a[1], as_ + kk * 512);
            lds2(a[2], a[3], as_ + kk * 512 + 16);
            float4 f0 = lds4f(ws + kk * 256);
            float4 f1 = lds4f(ws + kk * 256 + 16);
            const float fw[8] = {f0.x, f0.y, f0.z, f0.w, f1.x, f1.y, f1.z, f1.w};
#pragma unroll
            for (int j = 0; j < 8; j++) {
                u64 ww = pk2(fw[j], fw[j]);
#pragma unroll
                for (int i = 0; i < 4; i++)
                    acc[j][i] = ffma2(a[i], ww, acc[j][i]);
            }
        }
    };

    cpa_tile(0, kb0);
    ldW(kb0);
    stW(0);
    cpwait0();
    __syncthreads();
    for (int ti = 0; ti < nkt; ++ti) {
        int kb = kb0 + ((ti + 1) << 4);
        bool nx = (ti + 1) < nkt;
        if (nx) { cpa_tile((ti + 1) & 1, kb); ldW(kb); }
        compute(ti & 1);
        if (nx) { stW((ti + 1) & 1); cpwait0(); }
        __syncthreads();
    }

#pragma unroll
    for (int j = 0; j < 8; j++) {
        int l = l0 + 2 * (lc0 + j) + dlt;
        u64* o = g_st + (((size_t)m * MDIM) + l) * BCN + bc0 + bto;
        ulonglong2 w0, w1;
        w0.x = acc[j][0]; w0.y = acc[j][1];
        w1.x = acc[j][2]; w1.y = acc[j][3];
        *(ulonglong2*)o       = w0;
        *(ulonglong2*)(o + 2) = w1;
    }
}

// ---------------------------------------------------------------------------
// Transpose: out[bc][l][m] <- g_st[m][l][bc]; zero for l < m.
// ---------------------------------------------------------------------------
extern "C" __global__ void __launch_bounds__(256)
sht_transpose(u64* __restrict__ out)
{
    __shared__ u64 smt[32][65];
    const int t   = threadIdx.x;
    const int bc0 = blockIdx.x * 64;
    const int m0  = blockIdx.y * 32;
    const int l   = blockIdx.z;

    const int mr  = t >> 5;
    const int bcc = (t & 31) * 2;
#pragma unroll
    for (int r = 0; r < 4; ++r) {
        int ml = mr + r * 8;
        ulonglong2 v;
        if (l >= m0 + ml)
            v = *(const ulonglong2*)(g_st + (((size_t)(m0 + ml)) * MDIM + l) * BCN + bc0 + bcc);
        else
            v = make_ulonglong2(0ull, 0ull);
        smt[ml][bcc]     = v.x;
        smt[ml][bcc + 1] = v.y;
    }
    __syncthreads();

    const int bcr = t >> 4;
    const int mc  = (t & 15) * 2;
#pragma unroll
    for (int r = 0; r < 4; ++r) {
        int bcl = bcr + r * 16;
        ulonglong2 v;
        v.x = smt[mc][bcl];
        v.y = smt[mc + 1][bcl];
        *(ulonglong2*)(out + (((size_t)(bc0 + bcl)) * MDIM + l) * MDIM + m0 + mc) = v;
    }
}

// ---------------------------------------------------------------------------

extern "C" void kernel_launch(void* const* d_in, const int* in_sizes, int n_in,
                              void* d_out, int out_size)
{
    (void)in_sizes; (void)n_in; (void)out_size;
    const float* x      = (const float*)d_in[0];
    const float* weight = (const float*)d_in[1];
    const float* cosb   = (const float*)d_in[2];
    const float* sinb   = (const float*)d_in[3];

    dim3 gFX(64, 96);
    sht_foldx<<<gFX, 256>>>(x);

    sht_foldb<<<96, 256>>>(cosb, sinb);

    const int smemA = 81920;
    cudaFuncSetAttribute(sht_stageA, cudaFuncAttributeMaxDynamicSharedMemorySize, smemA);
    dim3 gA(3, 16, 96);
    sht_stageA<<<gA, 256, smemA>>>();

    dim3 gB(3, 16, 192);
    sht_stageB<<<gB, 128>>>(weight);

    dim3 gT(16, 6, 192);
    sht_transpose<<<gT, 256>>>((u64*)d_out);
}

// round 17
// speedup vs baseline: 1.2198x; 1.0633x over previous
#include <cuda_runtime.h>

#define NGRID   41088
#define PMAX    404
#define MDIM    192
#define KR      192
#define KF      96
#define BCN     1024
#define QPAD    128
#define XROWP   408
#define TWO_PI_F 6.28318530717958647692f

typedef unsigned long long u64;
typedef unsigned int u32;

// Pre-folded stage-A output: (re,im) pairs, layout [m][kf][bc], kf in [0,96)
__device__ u64 g_rip[(size_t)MDIM * KF * BCN];   // A+ (DFT of ring-sum)
__device__ u64 g_rim[(size_t)MDIM * KF * BCN];   // A- (DFT of ring-diff)
// Stage-B staging: (re,im) pairs, layout [m][l][bc]
__device__ u64 g_st[(size_t)MDIM * MDIM * BCN];
// Double-folded x streams: [k1][q][par*2+pm][bc], u64 = (XA,XB) / (XC,XD)
__device__ u64 g_xf[(size_t)KF * QPAD * 4 * BCN];
// Folded basis: [k1][q][par][mc], u64 = (cos, sin)
__device__ u64 g_bf[(size_t)KF * QPAD * 2 * 96];

__device__ __forceinline__ u64 ffma2(u64 a, u64 b, u64 c) {
    u64 d; asm("fma.rn.f32x2 %0,%1,%2,%3;" : "=l"(d) : "l"(a), "l"(b), "l"(c)); return d;
}
__device__ __forceinline__ u64 fmul2(u64 a, u64 b) {
    u64 d; asm("mul.rn.f32x2 %0,%1,%2;" : "=l"(d) : "l"(a), "l"(b)); return d;
}
__device__ __forceinline__ u64 pk2(float lo, float hi) {
    u64 r; asm("mov.b64 %0,{%1,%2};" : "=l"(r) : "f"(lo), "f"(hi)); return r;
}
__device__ __forceinline__ void lds2(u64& a, u64& b, u32 addr) {
    asm volatile("ld.shared.v2.u64 {%0,%1},[%2];" : "=l"(a), "=l"(b) : "r"(addr));
}
__device__ __forceinline__ float4 lds4f(u32 addr) {
    float4 v;
    asm volatile("ld.shared.v4.f32 {%0,%1,%2,%3},[%4];"
                 : "=f"(v.x), "=f"(v.y), "=f"(v.z), "=f"(v.w) : "r"(addr));
    return v;
}
__device__ __forceinline__ void sts1(u32 addr, float a) {
    asm volatile("st.shared.f32 [%0],%1;" :: "r"(addr), "f"(a));
}
__device__ __forceinline__ u32 s2u(const void* p) {
    u32 a; asm("{.reg .u64 t; cvta.to.shared.u64 t,%1; cvt.u32.u64 %0,t;}" : "=r"(a) : "l"(p)); return a;
}
__device__ __forceinline__ void cpa16(u32 dst, const void* src, int bytes) {
    asm volatile("cp.async.cg.shared.global [%0],[%1],16,%2;" :: "r"(dst), "l"(src), "r"(bytes));
}
__device__ __forceinline__ void cpcommit() { asm volatile("cp.async.commit_group;"); }
__device__ __forceinline__ void cpwait0()  { asm volatile("cp.async.wait_group 0;"); }
__device__ __forceinline__ void cpwait1()  { asm volatile("cp.async.wait_group 1;"); }

// ---------------------------------------------------------------------------
// Fold-x (coalesced): hemisphere ring fold + double DFT fold.
// ---------------------------------------------------------------------------
extern "C" __global__ void __launch_bounds__(256)
sht_foldx(const float* __restrict__ x)
{
    __shared__ float xs[32][XROWP];
    const int k1  = blockIdx.y;
    const int bc0 = blockIdx.x * 16;
    const int nlon = 24 + 4 * k1;
    const int half = nlon >> 1, h2 = half >> 1;
    const int slon1 = 2 * k1 * k1 + 22 * k1;
    const int q2r = k1 + 1;
    const int slon2 = NGRID - (2 * q2r * q2r + 22 * q2r);

    // phase 1: coalesced row staging
    {
        const int row = threadIdx.x >> 3;        // 0..31
        const int l8  = threadIdx.x & 7;
        const int bc  = bc0 + (row & 15);
        const int ring = row >> 4;
        const float* src = x + (size_t)bc * NGRID + (ring ? slon2 : slon1);
        for (int p = l8 * 4; p < nlon; p += 32)
            *(float4*)&xs[row][p] = *(const float4*)&src[p];
    }
    __syncthreads();

    // phase 2: fold + write (bc-contiguous lanes)
    const int bcl = threadIdx.x & 15;
    const int qs  = threadIdx.x >> 4;            // 0..15
    const float* r0 = xs[bcl];
    const float* r1 = xs[16 + bcl];
    u64* dst = g_xf + (size_t)k1 * QPAD * 4 * BCN + bc0 + bcl;

    for (int q = qs; q <= h2; q += 16) {
        float XA[2], XB[2], XC[2], XD[2];
#pragma unroll
        for (int r = 0; r < 2; r++) {
            const float* xr = r ? r1 : r0;
            float a = xr[q];
            if (q == 0) {
                float c = xr[half];
                XA[r] = a + c; XC[r] = a - c; XB[r] = 0.f; XD[r] = 0.f;
            } else if (q == h2) {
                float b = xr[nlon - q];
                XA[r] = a + b; XC[r] = a + b; XB[r] = a - b; XD[r] = a - b;
            } else {
                float b = xr[nlon - q];
                float c = xr[half - q], d = xr[half + q];
                float xpa = a + b, xma = a - b;
                float xpb = c + d, xmb = c - d;
                XA[r] = xpa + xpb; XB[r] = xma - xmb;
                XC[r] = xpa - xpb; XD[r] = xma + xmb;
            }
        }
        u64* dq = dst + (size_t)q * 4 * BCN;
        dq[0]       = pk2(XA[0] + XA[1], XB[0] + XB[1]);   // par0, y+
        dq[BCN]     = pk2(XA[0] - XA[1], XB[0] - XB[1]);   // par0, y-
        dq[2 * BCN] = pk2(XC[0] + XC[1], XD[0] + XD[1]);   // par1, y+
        dq[3 * BCN] = pk2(XC[0] - XC[1], XD[0] - XD[1]);   // par1, y-
    }
}

// ---------------------------------------------------------------------------
// Fold-basis: interleave (cos,sin) pairs, parity-compacted over m.
// ---------------------------------------------------------------------------
extern "C" __global__ void __launch_bounds__(256)
sht_foldb(const float* __restrict__ cosb, const float* __restrict__ sinb)
{
    const int k1 = blockIdx.x;
    const int h2 = (24 + 4 * k1) >> 2;
    const int t  = threadIdx.x;
    const int qr = t >> 4;
    const int mq = (t & 15) * 4;
    const float* cb = cosb + (size_t)k1 * PMAX * MDIM;
    const float* sn = sinb + (size_t)k1 * PMAX * MDIM;

    for (int q0 = 0; q0 <= h2; q0 += 16) {
        int q = q0 + qr;
        if (q > h2) continue;
#pragma unroll
        for (int ms = 0; ms < 3; ms++) {
            int m = ms * 64 + mq;
            float4 c4 = *(const float4*)(cb + (size_t)q * MDIM + m);
            float4 s4 = *(const float4*)(sn + (size_t)q * MDIM + m);
            u64* d = g_bf + (size_t)(k1 * QPAD + q) * 2 * 96;
            int mc = m >> 1;
            d[mc]          = pk2(c4.x, s4.x);
            d[mc + 1]      = pk2(c4.z, s4.z);
            d[96 + mc]     = pk2(c4.y, s4.y);
            d[96 + mc + 1] = pk2(c4.w, s4.w);
        }
    }
}

// ---------------------------------------------------------------------------
// Stage A: double-folded DFT GEMM, operands pre-folded in gmem.
// grid = (3 m-tiles, 16 bc-tiles, 96 pairs big-first).
// smem (80KB): CS[2][16q][2par][32mc u64] | XS[2][16q][2par][2pm][64bc u64]
// ---------------------------------------------------------------------------
extern "C" __global__ void __launch_bounds__(256, 2)
sht_stageA()
{
    extern __shared__ __align__(16) unsigned char smA[];   // 81920 B
    const int t   = threadIdx.x;
    const int m0  = blockIdx.x * 64;
    const int bc0 = blockIdx.y * 64;
    const int k1  = 95 - blockIdx.z;        // big rings first

    int mmax = 12 + 2 * k1;
    if (mmax > MDIM - 1) mmax = MDIM - 1;
    if (m0 > mmax) return;
    const int h2 = (24 + 4 * k1) >> 2;
    const int ntiles = (h2 + 16) >> 4;
    const int mc0 = m0 >> 1;

    const u32 sb = s2u(smA);
    const u32 XS = sb + 16384;

    const int w = t >> 5, lane = t & 31;
    const int par = w & 1, mch = (w >> 1) & 1, bw = w >> 2;
    const int lm = lane >> 3, lb = lane & 7;

    u64 acc0[4][4], acc1[4][4];
#pragma unroll
    for (int j = 0; j < 4; j++)
#pragma unroll
        for (int i = 0; i < 4; i++) { acc0[j][i] = 0ull; acc1[j][i] = 0ull; }

    auto cpa_tile = [&](int buf, int q0) {
#pragma unroll
        for (int i = 0; i < 2; i++) {       // CS: 512 chunks of 16B
            int c = t * 2 + i;
            int q = c >> 5, rest = c & 31;
            int pr = rest >> 4, ci = rest & 15;
            int qq = q0 + q;
            int bytes = (qq <= h2) ? 16 : 0;
            const u64* src = g_bf + ((size_t)(k1 * QPAD + qq) * 2 + pr) * 96 + mc0 + ci * 2;
            cpa16(sb + buf * 8192 + q * 512 + pr * 256 + ci * 16, src, bytes);
        }
#pragma unroll
        for (int i = 0; i < 8; i++) {       // XS: 2048 chunks of 16B
            int c = t * 8 + i;
            int q = c >> 7, rest = c & 127;
            int pp = rest >> 5, ci = rest & 31;
            int qq = q0 + q;
            int bytes = (qq <= h2) ? 16 : 0;
            const u64* src = g_xf + ((size_t)(k1 * QPAD + qq) * 4 + pp) * BCN + bc0 + ci * 2;
            cpa16(XS + buf * 32768 + q * 2048 + pp * 512 + ci * 16, src, bytes);
        }
        cpcommit();
    };

    auto compute = [&](int buf) {
        u32 cs = sb + buf * 8192 + par * 256 + (mch * 16 + lm * 4) * 8;
        u32 xs = XS + buf * 32768 + par * 1024 + bw * 256 + lb * 16;
#pragma unroll
        for (int qq = 0; qq < 16; ++qq) {
            u64 b0, b1, b2, b3;
            lds2(b0, b1, cs + qq * 512);
            lds2(b2, b3, cs + qq * 512 + 16);
            u64 v0, v1, v2, v3, u0, u1, u2, u3;
            lds2(v0, v1, xs + qq * 2048);
            lds2(v2, v3, xs + qq * 2048 + 128);
            lds2(u0, u1, xs + qq * 2048 + 512);
            lds2(u2, u3, xs + qq * 2048 + 640);
            acc0[0][0] = ffma2(b0, v0, acc0[0][0]);
            acc0[0][1] = ffma2(b0, v1, acc0[0][1]);
            acc0[0][2] = ffma2(b0, v2, acc0[0][2]);
            acc0[0][3] = ffma2(b0, v3, acc0[0][3]);
            acc0[1][0] = ffma2(b1, v0, acc0[1][0]);
            acc0[1][1] = ffma2(b1, v1, acc0[1][1]);
            acc0[1][2] = ffma2(b1, v2, acc0[1][2]);
            acc0[1][3] = ffma2(b1, v3, acc0[1][3]);
            acc0[2][0] = ffma2(b2, v0, acc0[2][0]);
            acc0[2][1] = ffma2(b2, v1, acc0[2][1]);
            acc0[2][2] = ffma2(b2, v2, acc0[2][2]);
            acc0[2][3] = ffma2(b2, v3, acc0[2][3]);
            acc0[3][0] = ffma2(b3, v0, acc0[3][0]);
            acc0[3][1] = ffma2(b3, v1, acc0[3][1]);
            acc0[3][2] = ffma2(b3, v2, acc0[3][2]);
            acc0[3][3] = ffma2(b3, v3, acc0[3][3]);
            acc1[0][0] = ffma2(b0, u0, acc1[0][0]);
            acc1[0][1] = ffma2(b0, u1, acc1[0][1]);
            acc1[0][2] = ffma2(b0, u2, acc1[0][2]);
            acc1[0][3] = ffma2(b0, u3, acc1[0][3]);
            acc1[1][0] = ffma2(b1, u0, acc1[1][0]);
            acc1[1][1] = ffma2(b1, u1, acc1[1][1]);
            acc1[1][2] = ffma2(b1, u2, acc1[1][2]);
            acc1[1][3] = ffma2(b1, u3, acc1[1][3]);
            acc1[2][0] = ffma2(b2, u0, acc1[2][0]);
            acc1[2][1] = ffma2(b2, u1, acc1[2][1]);
            acc1[2][2] = ffma2(b2, u2, acc1[2][2]);
            acc1[2][3] = ffma2(b2, u3, acc1[2][3]);
            acc1[3][0] = ffma2(b3, u0, acc1[3][0]);
            acc1[3][1] = ffma2(b3, u1, acc1[3][1]);
            acc1[3][2] = ffma2(b3, u2, acc1[3][2]);
            acc1[3][3] = ffma2(b3, u3, acc1[3][3]);
        }
    };

    cpa_tile(0, 0);
    for (int ti = 0; ti < ntiles; ++ti) {
        bool nx = (ti + 1) < ntiles;
        if (nx) { cpa_tile((ti + 1) & 1, (ti + 1) << 4); cpwait1(); }
        else    { cpwait0(); }
        __syncthreads();
        compute(ti & 1);
        __syncthreads();
    }

    const u64 tp2 = pk2(TWO_PI_F, TWO_PI_F);
#pragma unroll
    for (int j = 0; j < 4; j++) {
        int m = m0 + 2 * (mch * 16 + lm * 4 + j) + par;
        size_t base = ((size_t)m * KF + k1) * BCN + bc0 + bw * 32 + 2 * lb;
        u64* op = g_rip + base;
        u64* om = g_rim + base;
        ulonglong2 wp0, wp1, wm0, wm1;
        wp0.x = fmul2(acc0[j][0], tp2);
        wp0.y = fmul2(acc0[j][1], tp2);
        wp1.x = fmul2(acc0[j][2], tp2);
        wp1.y = fmul2(acc0[j][3], tp2);
        wm0.x = fmul2(acc1[j][0], tp2);
        wm0.y = fmul2(acc1[j][1], tp2);
        wm1.x = fmul2(acc1[j][2], tp2);
        wm1.y = fmul2(acc1[j][3], tp2);
        *(ulonglong2*)op        = wp0;
        *(ulonglong2*)(op + 16) = wp1;
        *(ulonglong2*)om        = wm0;
        *(ulonglong2*)(om + 16) = wm1;
    }
}

// ---------------------------------------------------------------------------
// Stage B: per-m GEMM on pre-folded operands, parity-coherent warps.
// grid = (3 l-tiles, 16 bc-tiles, 192 m).
// A-operand loads are 128B-contiguous 1-WF accesses: thread bc pairs
// {2lb, 2lb+1} and {2lb+16*.., } via bto = h*32 + (lane&7)*2, offsets +0/+128.
// ---------------------------------------------------------------------------
extern "C" __global__ void __launch_bounds__(128, 4)
sht_stageB(const float* __restrict__ weight)
{
    __shared__ __align__(16) unsigned char sm[4 * 16 * 512 + 2 * 16 * 256];  // 40960
    const int t   = threadIdx.x;
    const int l0  = blockIdx.x * 64;
    const int bc0 = blockIdx.y * 64;
    const int m   = blockIdx.z;
    if (l0 + 63 < m) return;                // zero triangle: handled by transpose

    const int klo = (m <= 12) ? 0 : ((m - 11) >> 1);
    const int kb0 = klo & ~15;
    const int nkt = ((95 - kb0) >> 4) + 1;

    const u32 sb  = s2u(sm);
    const u32 APS = sb;
    const u32 AMS = sb + 16384;
    const u32 WS  = sb + 32768;

    const int lr = t >> 1, kq = (t & 1) * 8;
    const int wpar = (lr + m) & 1, wlc = lr >> 1;

    const int w = t >> 5, lane = t & 31;
    const int pw  = w & 1;
    const int h   = w >> 1;
    const int lc0 = (lane >> 3) * 8;
    const int bto = h * 32 + (lane & 7) * 2;   // bc pairs {bto,bto+1},{bto+16,bto+17}
    const int dlt = pw ^ (m & 1);

    const float* wrow   = weight + ((size_t)m * MDIM + l0 + lr) * KR;
    const u64*   apbase = g_rip + ((size_t)m * KF) * BCN + bc0;
    const u64*   ambase = g_rim + ((size_t)m * KF) * BCN + bc0;

    u64 acc[8][4];
#pragma unroll
    for (int j = 0; j < 8; j++)
#pragma unroll
        for (int i = 0; i < 4; i++) acc[j][i] = 0ull;

    float4 w40, w41;
    auto cpa_tile = [&](int buf, int kb) {
#pragma unroll
        for (int c = 0; c < 4; c++) {
            int chunk = t * 4 + c;
            int kk = chunk >> 5, col = chunk & 31;
            int kg = kb + kk;
            int bytes = (kg >= klo) ? 16 : 0;
            cpa16(APS + buf * 8192 + kk * 512 + col * 16,
                  apbase + (size_t)kg * BCN + col * 2, bytes);
            cpa16(AMS + buf * 8192 + kk * 512 + col * 16,
                  ambase + (size_t)kg * BCN + col * 2, bytes);
        }
        cpcommit();
    };
    auto ldW = [&](int kb) {
        w40 = *(const float4*)(wrow + kb + kq);
        w41 = *(const float4*)(wrow + kb + kq + 4);
    };
    auto stW = [&](int buf) {
        u32 ws = WS + buf * 4096 + wpar * 128 + wlc * 4;
        sts1(ws + (kq + 0) * 256, w40.x);
        sts1(ws + (kq + 1) * 256, w40.y);
        sts1(ws + (kq + 2) * 256, w40.z);
        sts1(ws + (kq + 3) * 256, w40.w);
        sts1(ws + (kq + 4) * 256, w41.x);
        sts1(ws + (kq + 5) * 256, w41.y);
        sts1(ws + (kq + 6) * 256, w41.z);
        sts1(ws + (kq + 7) * 256, w41.w);
    };

    const u32 AT = pw ? AMS : APS;

    auto compute = [&](int buf) {
        u32 as_ = AT + buf * 8192 + bto * 8;
        u32 ws  = WS + buf * 4096 + pw * 128 + lc0 * 4;
#pragma unroll
        for (int kk = 0; kk < 16; ++kk) {
            u64 a[4];
            lds2(a[0], a[1], as_ + kk * 512);          // bc {bto, bto+1}
            lds2(a[2], a[3], as_ + kk * 512 + 128);    // bc {bto+16, bto+17}
            float4 f0 = lds4f(ws + kk * 256);
            float4 f1 = lds4f(ws + kk * 256 + 16);
            const float fw[8] = {f0.x, f0.y, f0.z, f0.w, f1.x, f1.y, f1.z, f1.w};
#pragma unroll
            for (int j = 0; j < 8; j++) {
                u64 ww = pk2(fw[j], fw[j]);
#pragma unroll
                for (int i = 0; i < 4; i++)
                    acc[j][i] = ffma2(a[i], ww, acc[j][i]);
            }
        }
    };

    cpa_tile(0, kb0);
    ldW(kb0);
    stW(0);
    cpwait0();
    __syncthreads();
    for (int ti = 0; ti < nkt; ++ti) {
        int kb = kb0 + ((ti + 1) << 4);
        bool nx = (ti + 1) < nkt;
        if (nx) { cpa_tile((ti + 1) & 1, kb); ldW(kb); }
        compute(ti & 1);
        if (nx) { stW((ti + 1) & 1); cpwait0(); }
        __syncthreads();
    }

#pragma unroll
    for (int j = 0; j < 8; j++) {
        int l = l0 + 2 * (lc0 + j) + dlt;
        u64* o = g_st + (((size_t)m * MDIM) + l) * BCN + bc0 + bto;
        ulonglong2 w0, w1;
        w0.x = acc[j][0]; w0.y = acc[j][1];
        w1.x = acc[j][2]; w1.y = acc[j][3];
        *(ulonglong2*)o        = w0;
        *(ulonglong2*)(o + 16) = w1;
    }
}

// ---------------------------------------------------------------------------
// Transpose: out[bc][l][m] <- g_st[m][l][bc]; zero for l < m.
// ---------------------------------------------------------------------------
extern "C" __global__ void __launch_bounds__(256)
sht_transpose(u64* __restrict__ out)
{
    __shared__ u64 smt[32][65];
    const int t   = threadIdx.x;
    const int bc0 = blockIdx.x * 64;
    const int m0  = blockIdx.y * 32;
    const int l   = blockIdx.z;

    const int mr  = t >> 5;
    const int bcc = (t & 31) * 2;
#pragma unroll
    for (int r = 0; r < 4; ++r) {
        int ml = mr + r * 8;
        ulonglong2 v;
        if (l >= m0 + ml)
            v = *(const ulonglong2*)(g_st + (((size_t)(m0 + ml)) * MDIM + l) * BCN + bc0 + bcc);
        else
            v = make_ulonglong2(0ull, 0ull);
        smt[ml][bcc]     = v.x;
        smt[ml][bcc + 1] = v.y;
    }
    __syncthreads();

    const int bcr = t >> 4;
    const int mc  = (t & 15) * 2;
#pragma unroll
    for (int r = 0; r < 4; ++r) {
        int bcl = bcr + r * 16;
        ulonglong2 v;
        v.x = smt[mc][bcl];
        v.y = smt[mc + 1][bcl];
        *(ulonglong2*)(out + (((size_t)(bc0 + bcl)) * MDIM + l) * MDIM + m0 + mc) = v;
    }
}

// ---------------------------------------------------------------------------

extern "C" void kernel_launch(void* const* d_in, const int* in_sizes, int n_in,
                              void* d_out, int out_size)
{
    (void)in_sizes; (void)n_in; (void)out_size;
    const float* x      = (const float*)d_in[0];
    const float* weight = (const float*)d_in[1];
    const float* cosb   = (const float*)d_in[2];
    const float* sinb   = (const float*)d_in[3];

    dim3 gFX(64, 96);
    sht_foldx<<<gFX, 256>>>(x);

    sht_foldb<<<96, 256>>>(cosb, sinb);

    const int smemA = 81920;
    cudaFuncSetAttribute(sht_stageA, cudaFuncAttributeMaxDynamicSharedMemorySize, smemA);
    dim3 gA(3, 16, 96);
    sht_stageA<<<gA, 256, smemA>>>();

    dim3 gB(3, 16, 192);
    sht_stageB<<<gB, 128>>>(weight);

    dim3 gT(16, 6, 192);
    sht_transpose<<<gT, 256>>>((u64*)d_out);
}